// round 15
// baseline (speedup 1.0000x reference)
#include <cuda_runtime.h>
#include <math.h>

#define TT 512
#define DD 64
#define NPAIR 60
#define NGRP 44
#define BIGV 1000000000.0f
#define C1E 0.28853900817779268f   // log2(e)/gamma, gamma=5
#define C2L 3.4657359027997265f    // gamma*ln(2)
#define RING 96                    // ring columns per band (covers live span 94)
#define LAG 5                      // supersteps of inter-band lag (from 63-row skew)
#define XTRA 4                     // extra handoff slack supersteps for half 1

#define NDTW (NPAIR * 2)           // 120 DTW half-blocks

// -------- device scratch --------
// tiled cost: addr(p,i,j) = p*512*512 + (i>>5)*(512*32) + j*32 + (i&31)
__device__ float g_costT[(size_t)NPAIR * TT * TT];   // ~63 MB
__device__ float g_G[NGRP * NGRP];
__device__ float g_sdt[NPAIR];
__device__ float g_bndX[NPAIR * TT];   // band3->band4 boundary rows (row 255 values)
__device__ int   g_prog[NPAIR];        // last exported superstep per pair

__constant__ int c_pi[9] = {0,0,0,1,1,2,2,3,3};
__constant__ int c_pj[9] = {1,2,3,2,3,1,3,1,2};

__device__ __forceinline__ float ex2f(float x) {
    float y; asm("ex2.approx.ftz.f32 %0, %1;" : "=f"(y) : "f"(x)); return y;
}
__device__ __forceinline__ float lg2f(float x) {
    float y; asm("lg2.approx.ftz.f32 %0, %1;" : "=f"(y) : "f"(x)); return y;
}

// softmin cell: d + softmin(a=diag, b=up, c=left); min/med/max form (ex2(0)==1)
__device__ __forceinline__ float cellf(float d, float a, float b, float c) {
    float mn2 = fminf(a, b), mx2 = fmaxf(a, b);
    float mn  = fminf(mn2, c);
    float mx  = fmaxf(mx2, c);
    float md  = fmaxf(mn2, fminf(mx2, c));
    float e   = 1.0f + ex2f((mn - md) * C1E) + ex2f((mn - mx) * C1E);
    return (d + mn) - C2L * lg2f(e);
}

// ======================= K1: cost matrices (128x64 tiles, 8x4 reg blocking) =======================
__global__ __launch_bounds__(256) void cost_kernel(const float* __restrict__ data,
                                                   const int* __restrict__ lens) {
    int p  = blockIdx.z;
    // reset handoff progress flags (stream-ordered before fused_kernel)
    if (blockIdx.x == 0 && blockIdx.y == 0 && threadIdx.x == 0) g_prog[p] = -1;

    int w  = p / 15;
    int jj = p % 15;
    int la = lens[w * 16];
    int lb = lens[w * 16 + 1 + jj];
    int row0 = blockIdx.y * 128;
    int col0 = blockIdx.x * 64;
    if (row0 >= la || col0 >= lb) return;

    const float* A = data + (size_t)(w * 16) * TT * DD;
    const float* B = data + (size_t)(w * 16 + 1 + jj) * TT * DD;

    __shared__ float As[64 * 132];  // [k][row 0..127], pad 132
    __shared__ float Bs[64 * 68];   // [k][row 0..63],  pad 68
    __shared__ float aN[128];
    __shared__ float bN[64];

    int tid = threadIdx.x;
    #pragma unroll
    for (int q = 0; q < 8; q++) {
        int idx = tid + q * 256;
        int r   = idx >> 4;
        int c4  = idx & 15;
        float4 va = *(const float4*)(A + (size_t)(row0 + r) * DD + c4 * 4);
        As[(c4*4+0)*132 + r] = va.x; As[(c4*4+1)*132 + r] = va.y;
        As[(c4*4+2)*132 + r] = va.z; As[(c4*4+3)*132 + r] = va.w;
    }
    #pragma unroll
    for (int q = 0; q < 4; q++) {
        int idx = tid + q * 256;
        int r   = idx >> 4;
        int c4  = idx & 15;
        float4 vb = *(const float4*)(B + (size_t)(col0 + r) * DD + c4 * 4);
        Bs[(c4*4+0)*68 + r] = vb.x; Bs[(c4*4+1)*68 + r] = vb.y;
        Bs[(c4*4+2)*68 + r] = vb.z; Bs[(c4*4+3)*68 + r] = vb.w;
    }
    __syncthreads();

    if (tid < 192) {
        int r = tid & 127;
        float s = 0.0f;
        if (tid < 128) {
            #pragma unroll 16
            for (int k = 0; k < 64; k++) { float v = As[k*132 + r]; s = fmaf(v, v, s); }
            aN[r] = s;
        } else {
            int rb = tid - 128;
            #pragma unroll 16
            for (int k = 0; k < 64; k++) { float v = Bs[k*68 + rb]; s = fmaf(v, v, s); }
            bN[rb] = s;
        }
    }

    int tx = tid & 15, ty = tid >> 4;
    float acc[8][4];
    #pragma unroll
    for (int i = 0; i < 8; i++)
        #pragma unroll
        for (int j = 0; j < 4; j++) acc[i][j] = 0.0f;

    #pragma unroll 4
    for (int k = 0; k < 64; k++) {
        float4 aA = *(const float4*)&As[k*132 + ty*8];
        float4 aB = *(const float4*)&As[k*132 + ty*8 + 4];
        float4 b4 = *(const float4*)&Bs[k*68 + tx*4];
        acc[0][0]=fmaf(aA.x,b4.x,acc[0][0]); acc[0][1]=fmaf(aA.x,b4.y,acc[0][1]);
        acc[0][2]=fmaf(aA.x,b4.z,acc[0][2]); acc[0][3]=fmaf(aA.x,b4.w,acc[0][3]);
        acc[1][0]=fmaf(aA.y,b4.x,acc[1][0]); acc[1][1]=fmaf(aA.y,b4.y,acc[1][1]);
        acc[1][2]=fmaf(aA.y,b4.z,acc[1][2]); acc[1][3]=fmaf(aA.y,b4.w,acc[1][3]);
        acc[2][0]=fmaf(aA.z,b4.x,acc[2][0]); acc[2][1]=fmaf(aA.z,b4.y,acc[2][1]);
        acc[2][2]=fmaf(aA.z,b4.z,acc[2][2]); acc[2][3]=fmaf(aA.z,b4.w,acc[2][3]);
        acc[3][0]=fmaf(aA.w,b4.x,acc[3][0]); acc[3][1]=fmaf(aA.w,b4.y,acc[3][1]);
        acc[3][2]=fmaf(aA.w,b4.z,acc[3][2]); acc[3][3]=fmaf(aA.w,b4.w,acc[3][3]);
        acc[4][0]=fmaf(aB.x,b4.x,acc[4][0]); acc[4][1]=fmaf(aB.x,b4.y,acc[4][1]);
        acc[4][2]=fmaf(aB.x,b4.z,acc[4][2]); acc[4][3]=fmaf(aB.x,b4.w,acc[4][3]);
        acc[5][0]=fmaf(aB.y,b4.x,acc[5][0]); acc[5][1]=fmaf(aB.y,b4.y,acc[5][1]);
        acc[5][2]=fmaf(aB.y,b4.z,acc[5][2]); acc[5][3]=fmaf(aB.y,b4.w,acc[5][3]);
        acc[6][0]=fmaf(aB.z,b4.x,acc[6][0]); acc[6][1]=fmaf(aB.z,b4.y,acc[6][1]);
        acc[6][2]=fmaf(aB.z,b4.z,acc[6][2]); acc[6][3]=fmaf(aB.z,b4.w,acc[6][3]);
        acc[7][0]=fmaf(aB.w,b4.x,acc[7][0]); acc[7][1]=fmaf(aB.w,b4.y,acc[7][1]);
        acc[7][2]=fmaf(aB.w,b4.z,acc[7][2]); acc[7][3]=fmaf(aB.w,b4.w,acc[7][3]);
    }
    __syncthreads();

    float an[8], bn[4];
    #pragma unroll
    for (int i = 0; i < 8; i++) an[i] = aN[ty*8 + i];
    #pragma unroll
    for (int j = 0; j < 4; j++) bn[j] = bN[tx*4 + j];

    float* stage = As;   // reuse as [128][65]
    #pragma unroll
    for (int i = 0; i < 8; i++)
        #pragma unroll
        for (int j = 0; j < 4; j++)
            stage[(ty*8 + i)*65 + tx*4 + j] = an[i] + bn[j] - 2.0f * acc[i][j];
    __syncthreads();

    float* outBase = g_costT + (size_t)p * TT * TT + (row0 >> 5) * (TT * 32) + col0 * 32;
    #pragma unroll
    for (int c = 0; c < 32; c++) {
        int idx  = tid + (c << 8);
        int lane = idx & 31;
        int colL = (idx >> 5) & 63;
        int rg   = idx >> 11;
        outBase[rg * (TT * 32) + colL * 32 + lane] = stage[(rg * 32 + lane)*65 + colL];
    }
}

// ======================= fused: split DTW (blocks 0..119) + Gram (120..240) =======================
// DTW half-block: 4 consumer warps (1 per SMSP) + 4 producer warps; 4 bands of 64 rows.
// Half 1 runs XTRA supersteps of extra lag so the gmem handoff from half 0 is
// always XTRA supersteps stale -> no lockstep coupling through L2.
__global__ __launch_bounds__(256, 1) void fused_kernel(const float* __restrict__ data,
                                                       const int* __restrict__ lens) {
    extern __shared__ float sm[];
    int bid = blockIdx.x;

    if (bid < NDTW) {
        int p    = bid >> 1;
        int half = bid & 1;
        int wi = p / 15, jj = p % 15;
        int la = lens[wi * 16];
        int lb = lens[wi * 16 + 1 + jj];
        int nBands = (la + 63) >> 6;
        int nSup   = LAG * (nBands - 1) + ((lb + 78) >> 4) + ((la > 256) ? XTRA : 0);
        int wid = threadIdx.x >> 5;
        int t   = threadIdx.x & 31;
        float* bnd = sm + 4 * (RING * 64);     // [5][128]

        int l = (wid < 4) ? wid : (wid - 4);   // local band 0..3
        int w = half * 4 + l;                  // global band
        bool activeBand = (w * 64 < la);
        int lagw = LAG * w + ((half == 1) ? XTRA : 0);

        if (wid < 4) {
            // ---------------- consumer: 2 rows per lane ----------------
            float* ringW = sm + l * (RING * 64);
            float r0 = BIGV, r1 = BIGV, r0p = BIGV, u0p = BIGV, dprev = 0.0f;
            int row0 = w * 64 + 2 * t;

            for (int sup = 0; sup < nSup; sup++) {
                __syncthreads();
                if (!activeBand) continue;
                int S = (sup - lagw) << 4;
                if (S < 0 || S >= lb + 63) continue;

                float bu[16];
                if (w > 0) {
                    #pragma unroll
                    for (int q = 0; q < 16; q++) bu[q] = bnd[l * 128 + ((S + q) & 127)];
                } else {
                    #pragma unroll
                    for (int q = 0; q < 16; q++) bu[q] = BIGV;
                }

                float2 dv[16];
                #pragma unroll
                for (int q = 0; q < 16; q++) {
                    int c0 = S + q - 2 * t;
                    int cm = c0 % RING; cm += (cm < 0) ? RING : 0;
                    dv[q] = *(const float2*)&ringW[cm * 64 + 2 * t];
                }

                #pragma unroll
                for (int q = 0; q < 16; q++) {
                    int c0 = S + q - 2 * t;
                    float u0 = __shfl_up_sync(0xffffffffu, r1, 1);
                    if (t == 0) u0 = bu[q];
                    float diag0 = u0p;
                    if (w == 0 && t == 0 && (S + q) == 0) diag0 = 0.0f;
                    float n0 = cellf(dv[q].x, diag0, u0, r0);
                    float n1 = cellf(dprev,  r0p,  r0, r1);
                    bool act0 = ((unsigned)c0 < (unsigned)lb);
                    bool act1 = ((unsigned)(c0 - 1) < (unsigned)lb);
                    r0p = r0;
                    if (act0) r0 = n0;
                    u0p = u0;
                    if (act1) r1 = n1;
                    dprev = dv[q].y;
                    if (act1 && t == 31) bnd[(l + 1) * 128 + ((c0 - 1) & 127)] = r1;
                }
            }
            if (activeBand) {
                if (row0 == la - 1)     g_sdt[p] = r0;
                if (row0 + 1 == la - 1) g_sdt[p] = r1;
            }
        } else {
            // ---------------- producer: pipelined ring prefetch (+import/export) ----------------
            float* ringP = sm + l * (RING * 64);
            const float* Cp0 = g_costT + (size_t)p * TT * TT + (2 * w) * (TT * 32);
            const float* Cp1 = Cp0 + TT * 32;

            // prologue: global band 0, columns 0..15 (stored directly, before loop)
            if (activeBand && w == 0) {
                const float4* s0 = (const float4*)Cp0;
                const float4* s1 = (const float4*)Cp1;
                #pragma unroll
                for (int k = 0; k < 4; k++) {
                    int i = t + 32 * k;
                    float4 v0 = s0[i];
                    float4 v1 = s1[i];
                    int col = (i >> 3);
                    int r4  = (i & 7) << 2;
                    *(float4*)&ringP[col * 64 + r4]      = v0;
                    *(float4*)&ringP[col * 64 + 32 + r4] = v1;
                }
            }

            // preload chunk to be stored at sup=0 (valid only for w==0: cS=16)
            float4 v0r[4], v1r[4];
            int  chunkCS = (0 - lagw) * 16 + 16;
            bool haveChunk = activeBand && (chunkCS >= 0) && (chunkCS < lb);
            if (haveChunk) {
                const float4* s0 = (const float4*)(Cp0 + chunkCS * 32);
                const float4* s1 = (const float4*)(Cp1 + chunkCS * 32);
                #pragma unroll
                for (int k = 0; k < 4; k++) { int i = t + 32 * k; v0r[k] = s0[i]; v1r[k] = s1[i]; }
            }

            for (int sup = 0; sup < nSup; sup++) {
                __syncthreads();

                // importer: block (p,1), band 4: fill bnd[0] for consumer's NEXT superstep.
                // With XTRA slack the needed export is XTRA supersteps old: first poll passes.
                if (half == 1 && l == 0 && la > 256) {
                    int Snext = ((sup + 1) - lagw) << 4;     // lagw = 20 + XTRA
                    if (Snext >= 0 && Snext < lb) {
                        while (*(volatile int*)&g_prog[p] < sup - XTRA) __nanosleep(64);
                        __threadfence();
                        int c = Snext + t;
                        if (t < 16 && c < lb) bnd[(c & 127)] = g_bndX[p * TT + c];
                    }
                }

                // store the chunk loaded during the previous superstep (issue-only)
                if (haveChunk) {
                    #pragma unroll
                    for (int k = 0; k < 4; k++) {
                        int i   = t + 32 * k;
                        int col = chunkCS + (i >> 3);
                        int cm  = col % RING;
                        int r4  = (i & 7) << 2;
                        *(float4*)&ringP[cm * 64 + r4]      = v0r[k];
                        *(float4*)&ringP[cm * 64 + 32 + r4] = v1r[k];
                    }
                }

                // issue LDG for the chunk to store next superstep (latency hidden)
                chunkCS   = ((sup + 1) - lagw) * 16 + 16;
                haveChunk = activeBand && (chunkCS >= 0) && (chunkCS < lb);
                if (haveChunk) {
                    const float4* s0 = (const float4*)(Cp0 + chunkCS * 32);
                    const float4* s1 = (const float4*)(Cp1 + chunkCS * 32);
                    #pragma unroll
                    for (int k = 0; k < 4; k++) { int i = t + 32 * k; v0r[k] = s0[i]; v1r[k] = s1[i]; }
                }

                // exporter: block (p,0), band 3: publish cols written last superstep
                if (half == 0 && l == 3 && la > 256) {
                    int S3 = ((sup - 1) - lagw) << 4;        // lagw = 15
                    int c  = S3 - 63 + t;
                    if (t < 16 && c >= 0 && c < lb) g_bndX[p * TT + c] = bnd[4 * 128 + (c & 127)];
                    __threadfence();
                    if (t == 0) atomicExch(&g_prog[p], sup - 1);
                }
            }
        }
    } else {
        // ---------------- Gram of 44 group vectors (256 threads) ----------------
        int g  = bid - NDTW;                 // 0..120
        int bi = g / 11, bj = g % 11;
        int tid = threadIdx.x;
        const float4* pa[4];
        const float4* pb[4];
        #pragma unroll
        for (int a = 0; a < 4; a++) {
            int ga = bi * 4 + a; int ra = (ga / 11) * 16 + (ga % 11);
            pa[a] = (const float4*)(data + (size_t)ra * TT * DD);
            int gb = bj * 4 + a; int rb = (gb / 11) * 16 + (gb % 11);
            pb[a] = (const float4*)(data + (size_t)rb * TT * DD);
        }
        float acc[4][4];
        #pragma unroll
        for (int a = 0; a < 4; a++)
            #pragma unroll
            for (int b = 0; b < 4; b++) acc[a][b] = 0.0f;

        for (int it = tid; it < TT * DD / 4; it += 256) {
            float4 xa[4], xb[4];
            #pragma unroll
            for (int a = 0; a < 4; a++) xa[a] = pa[a][it];
            #pragma unroll
            for (int b = 0; b < 4; b++) xb[b] = pb[b][it];
            #pragma unroll
            for (int a = 0; a < 4; a++)
                #pragma unroll
                for (int b = 0; b < 4; b++)
                    acc[a][b] += fmaf(xa[a].x, xb[b].x, fmaf(xa[a].y, xb[b].y,
                                 fmaf(xa[a].z, xb[b].z, xa[a].w * xb[b].w)));
        }
        #pragma unroll
        for (int a = 0; a < 4; a++)
            #pragma unroll
            for (int b = 0; b < 4; b++) {
                float v = acc[a][b];
                #pragma unroll
                for (int o = 16; o > 0; o >>= 1) v += __shfl_down_sync(0xffffffffu, v, o);
                acc[a][b] = v;
            }
        int wq = tid >> 5, lane = tid & 31;
        if (lane == 0) {
            #pragma unroll
            for (int a = 0; a < 4; a++)
                #pragma unroll
                for (int b = 0; b < 4; b++) sm[wq * 16 + a * 4 + b] = acc[a][b];
        }
        __syncthreads();
        if (tid < 16) {
            float s = 0.0f;
            #pragma unroll
            for (int ww = 0; ww < 8; ww++) s += sm[ww * 16 + tid];
            int a = tid >> 2, b = tid & 3;
            g_G[(bi * 4 + a) * NGRP + bj * 4 + b] = s;
        }
    }
}

// ======================= MMD (9 warps) + finalize, one block =======================
__global__ __launch_bounds__(512) void mmd_final_kernel(const int* __restrict__ lens,
                                                        float* __restrict__ out) {
    __shared__ float l2s[9][484];
    __shared__ float s_mmd[9];
    int tid  = threadIdx.x;
    int wp   = tid >> 5;
    int lane = tid & 31;

    if (wp < 9) {
        int wa = c_pi[wp], wb = c_pj[wp];
        float part = 0.0f;
        #pragma unroll
        for (int q = 0; q < 16; q++) {
            int e = lane + q * 32;
            if (e < 484) {
                int a = e / 22, b = e % 22;
                int ga = (a < 11) ? wa * 11 + a : wb * 11 + (a - 11);
                int gb = (b < 11) ? wa * 11 + b : wb * 11 + (b - 11);
                float l2 = g_G[ga * NGRP + ga] + g_G[gb * NGRP + gb]
                         - 2.0f * g_G[ga * NGRP + gb];
                l2s[wp][e] = l2;
                part += l2;
            }
        }
        #pragma unroll
        for (int o = 16; o > 0; o >>= 1) part += __shfl_down_sync(0xffffffffu, part, o);
        float bw = __shfl_sync(0xffffffffu, part, 0) / (22.0f * 22.0f - 22.0f) / 4.0f;
        __syncwarp();

        float part2 = 0.0f;
        #pragma unroll
        for (int q = 0; q < 4; q++) {
            int e = lane + q * 32;
            if (e < 121) {
                int u = e / 11, v = e % 11;
                float lxx = l2s[wp][u * 22 + v];
                float lyy = l2s[wp][(u + 11) * 22 + (v + 11)];
                float lxy = l2s[wp][u * 22 + (v + 11)];
                float lyx = l2s[wp][(u + 11) * 22 + v];
                #pragma unroll
                for (int kk = 0; kk < 5; kk++) {
                    float ib = 1.0f / (bw * (float)(1 << kk));
                    part2 += __expf(-lxx * ib) + __expf(-lyy * ib)
                           - __expf(-lxy * ib) - __expf(-lyx * ib);
                }
            }
        }
        #pragma unroll
        for (int o = 16; o > 0; o >>= 1) part2 += __shfl_down_sync(0xffffffffu, part2, o);
        if (lane == 0) s_mmd[wp] = part2 / 121.0f;
    }
    __syncthreads();

    if (tid == 0) {
        float total = 0.0f;
        for (int w = 0; w < 4; w++) {
            float la = (float)lens[w * 16];
            float dg[6], dn[9];
            for (int j = 0; j < 15; j++) {
                float lb = (float)lens[w * 16 + 1 + j];
                float dist = g_sdt[w * 15 + j] / (la + lb);
                if (j < 6) dg[j] = dist; else dn[j - 6] = dist;
            }
            float ca = 0.0f;
            for (int j = 0; j < 6; j++) ca += dg[j];
            ca *= (1.0f / 6.0f);
            float cb = 0.0f;
            for (int j = 0; j < 5; j++) cb += dn[j];
            cb *= (1.0f / 5.0f);
            float lkSum = 0.0f;
            int nz = 0;
            for (int g = 0; g < 6; g++)
                for (int n = 0; n < 9; n++) {
                    float v = dg[g] + 1.0f - dn[n];
                    if (v > 0.0f) { lkSum += v; nz++; }
                }
            float intra = 0.0f;
            for (int g = 0; g < 6; g++) intra += dg[g] - ca;
            float inter = 1.0f - fabsf(ca - cb);
            if (inter < 0.0f) inter = 0.0f;
            total += lkSum / (float)(nz + 1) + intra * 0.1f + inter * 0.1f;
        }
        total *= 0.25f;
        float mx = 0.0f;
        for (int p = 0; p < 9; p++) mx = fmaxf(mx, s_mmd[p]);
        out[0] = total + mx * 0.01f;
    }
}

// ======================= launch =======================
extern "C" void kernel_launch(void* const* d_in, const int* in_sizes, int n_in,
                              void* d_out, int out_size) {
    const float* data = (const float*)d_in[0];
    const int*   lens = (const int*)d_in[1];
    float*       out  = (float*)d_out;

    // DTW half-block uses 4 rings (98304 B) + bnd 2560 B; request 200704 B to
    // force 1 block/SM (1 consumer warp per SMSP).
    cudaFuncSetAttribute(fused_kernel, cudaFuncAttributeMaxDynamicSharedMemorySize, 200704);

    cost_kernel<<<dim3(8, 4, NPAIR), 256>>>(data, lens);
    fused_kernel<<<NDTW + 121, 256, 200704>>>(data, lens);
    mmd_final_kernel<<<1, 512>>>(lens, out);
}

// round 16
// speedup vs baseline: 1.0475x; 1.0475x over previous
#include <cuda_runtime.h>
#include <math.h>

#define TT 512
#define DD 64
#define NPAIR 60
#define NGRP 44
#define BIGV 1000000000.0f
#define C1E 0.28853900817779268f   // log2(e)/gamma, gamma=5
#define C2L 3.4657359027997265f    // gamma*ln(2)
#define RING 128                   // ring columns per band (power of 2; live span 94)
#define LAG 5                      // supersteps of inter-band lag (from 63-row skew)

#define NDTW (NPAIR * 2)           // 120 DTW half-blocks

// -------- device scratch --------
// tiled cost: addr(p,i,j) = p*512*512 + (i>>5)*(512*32) + j*32 + (i&31)
__device__ float g_costT[(size_t)NPAIR * TT * TT];   // ~63 MB
__device__ float g_G[NGRP * NGRP];
__device__ float g_sdt[NPAIR];
__device__ float g_bndX[NPAIR * TT];   // band3->band4 boundary rows (row 255 values)
__device__ int   g_prog[NPAIR];        // last exported superstep per pair

__constant__ int c_pi[9] = {0,0,0,1,1,2,2,3,3};
__constant__ int c_pj[9] = {1,2,3,2,3,1,3,1,2};

__device__ __forceinline__ float ex2f(float x) {
    float y; asm("ex2.approx.ftz.f32 %0, %1;" : "=f"(y) : "f"(x)); return y;
}
__device__ __forceinline__ float lg2f(float x) {
    float y; asm("lg2.approx.ftz.f32 %0, %1;" : "=f"(y) : "f"(x)); return y;
}

// softmin cell: d + softmin(a=diag, b=up, c=left); min/med/max form (ex2(0)==1)
__device__ __forceinline__ float cellf(float d, float a, float b, float c) {
    float mn2 = fminf(a, b), mx2 = fmaxf(a, b);
    float mn  = fminf(mn2, c);
    float mx  = fmaxf(mx2, c);
    float md  = fmaxf(mn2, fminf(mx2, c));
    float e   = 1.0f + ex2f((mn - md) * C1E) + ex2f((mn - mx) * C1E);
    return (d + mn) - C2L * lg2f(e);
}

// ======================= K1: cost matrices (128x64 tiles, 8x4 reg blocking) =======================
__global__ __launch_bounds__(256) void cost_kernel(const float* __restrict__ data,
                                                   const int* __restrict__ lens) {
    int p  = blockIdx.z;
    // reset handoff progress flags (stream-ordered before fused_kernel)
    if (blockIdx.x == 0 && blockIdx.y == 0 && threadIdx.x == 0) g_prog[p] = -1;

    int w  = p / 15;
    int jj = p % 15;
    int la = lens[w * 16];
    int lb = lens[w * 16 + 1 + jj];
    int row0 = blockIdx.y * 128;
    int col0 = blockIdx.x * 64;
    if (row0 >= la || col0 >= lb) return;

    const float* A = data + (size_t)(w * 16) * TT * DD;
    const float* B = data + (size_t)(w * 16 + 1 + jj) * TT * DD;

    __shared__ float As[64 * 132];  // [k][row 0..127], pad 132
    __shared__ float Bs[64 * 68];   // [k][row 0..63],  pad 68
    __shared__ float aN[128];
    __shared__ float bN[64];

    int tid = threadIdx.x;
    #pragma unroll
    for (int q = 0; q < 8; q++) {
        int idx = tid + q * 256;
        int r   = idx >> 4;
        int c4  = idx & 15;
        float4 va = *(const float4*)(A + (size_t)(row0 + r) * DD + c4 * 4);
        As[(c4*4+0)*132 + r] = va.x; As[(c4*4+1)*132 + r] = va.y;
        As[(c4*4+2)*132 + r] = va.z; As[(c4*4+3)*132 + r] = va.w;
    }
    #pragma unroll
    for (int q = 0; q < 4; q++) {
        int idx = tid + q * 256;
        int r   = idx >> 4;
        int c4  = idx & 15;
        float4 vb = *(const float4*)(B + (size_t)(col0 + r) * DD + c4 * 4);
        Bs[(c4*4+0)*68 + r] = vb.x; Bs[(c4*4+1)*68 + r] = vb.y;
        Bs[(c4*4+2)*68 + r] = vb.z; Bs[(c4*4+3)*68 + r] = vb.w;
    }
    __syncthreads();

    if (tid < 192) {
        int r = tid & 127;
        float s = 0.0f;
        if (tid < 128) {
            #pragma unroll 16
            for (int k = 0; k < 64; k++) { float v = As[k*132 + r]; s = fmaf(v, v, s); }
            aN[r] = s;
        } else {
            int rb = tid - 128;
            #pragma unroll 16
            for (int k = 0; k < 64; k++) { float v = Bs[k*68 + rb]; s = fmaf(v, v, s); }
            bN[rb] = s;
        }
    }

    int tx = tid & 15, ty = tid >> 4;
    float acc[8][4];
    #pragma unroll
    for (int i = 0; i < 8; i++)
        #pragma unroll
        for (int j = 0; j < 4; j++) acc[i][j] = 0.0f;

    #pragma unroll 4
    for (int k = 0; k < 64; k++) {
        float4 aA = *(const float4*)&As[k*132 + ty*8];
        float4 aB = *(const float4*)&As[k*132 + ty*8 + 4];
        float4 b4 = *(const float4*)&Bs[k*68 + tx*4];
        acc[0][0]=fmaf(aA.x,b4.x,acc[0][0]); acc[0][1]=fmaf(aA.x,b4.y,acc[0][1]);
        acc[0][2]=fmaf(aA.x,b4.z,acc[0][2]); acc[0][3]=fmaf(aA.x,b4.w,acc[0][3]);
        acc[1][0]=fmaf(aA.y,b4.x,acc[1][0]); acc[1][1]=fmaf(aA.y,b4.y,acc[1][1]);
        acc[1][2]=fmaf(aA.y,b4.z,acc[1][2]); acc[1][3]=fmaf(aA.y,b4.w,acc[1][3]);
        acc[2][0]=fmaf(aA.z,b4.x,acc[2][0]); acc[2][1]=fmaf(aA.z,b4.y,acc[2][1]);
        acc[2][2]=fmaf(aA.z,b4.z,acc[2][2]); acc[2][3]=fmaf(aA.z,b4.w,acc[2][3]);
        acc[3][0]=fmaf(aA.w,b4.x,acc[3][0]); acc[3][1]=fmaf(aA.w,b4.y,acc[3][1]);
        acc[3][2]=fmaf(aA.w,b4.z,acc[3][2]); acc[3][3]=fmaf(aA.w,b4.w,acc[3][3]);
        acc[4][0]=fmaf(aB.x,b4.x,acc[4][0]); acc[4][1]=fmaf(aB.x,b4.y,acc[4][1]);
        acc[4][2]=fmaf(aB.x,b4.z,acc[4][2]); acc[4][3]=fmaf(aB.x,b4.w,acc[4][3]);
        acc[5][0]=fmaf(aB.y,b4.x,acc[5][0]); acc[5][1]=fmaf(aB.y,b4.y,acc[5][1]);
        acc[5][2]=fmaf(aB.y,b4.z,acc[5][2]); acc[5][3]=fmaf(aB.y,b4.w,acc[5][3]);
        acc[6][0]=fmaf(aB.z,b4.x,acc[6][0]); acc[6][1]=fmaf(aB.z,b4.y,acc[6][1]);
        acc[6][2]=fmaf(aB.z,b4.z,acc[6][2]); acc[6][3]=fmaf(aB.z,b4.w,acc[6][3]);
        acc[7][0]=fmaf(aB.w,b4.x,acc[7][0]); acc[7][1]=fmaf(aB.w,b4.y,acc[7][1]);
        acc[7][2]=fmaf(aB.w,b4.z,acc[7][2]); acc[7][3]=fmaf(aB.w,b4.w,acc[7][3]);
    }
    __syncthreads();

    float an[8], bn[4];
    #pragma unroll
    for (int i = 0; i < 8; i++) an[i] = aN[ty*8 + i];
    #pragma unroll
    for (int j = 0; j < 4; j++) bn[j] = bN[tx*4 + j];

    float* stage = As;   // reuse as [128][65]
    #pragma unroll
    for (int i = 0; i < 8; i++)
        #pragma unroll
        for (int j = 0; j < 4; j++)
            stage[(ty*8 + i)*65 + tx*4 + j] = an[i] + bn[j] - 2.0f * acc[i][j];
    __syncthreads();

    float* outBase = g_costT + (size_t)p * TT * TT + (row0 >> 5) * (TT * 32) + col0 * 32;
    #pragma unroll
    for (int c = 0; c < 32; c++) {
        int idx  = tid + (c << 8);
        int lane = idx & 31;
        int colL = (idx >> 5) & 63;
        int rg   = idx >> 11;
        outBase[rg * (TT * 32) + colL * 32 + lane] = stage[(rg * 32 + lane)*65 + colL];
    }
}

// ======================= fused: split DTW (blocks 0..119) + Gram (120..240) =======================
// DTW half-block: 4 consumer warps (1 per SMSP) + 4 producer warps; 4 bands of 64 rows.
// RING=128 (power-of-2 indexing) + interior fast path (no guards) in the consumer.
__global__ __launch_bounds__(256, 1) void fused_kernel(const float* __restrict__ data,
                                                       const int* __restrict__ lens) {
    extern __shared__ float sm[];
    int bid = blockIdx.x;

    if (bid < NDTW) {
        int p    = bid >> 1;
        int half = bid & 1;
        int wi = p / 15, jj = p % 15;
        int la = lens[wi * 16];
        int lb = lens[wi * 16 + 1 + jj];
        int nBands = (la + 63) >> 6;
        int nSup   = LAG * (nBands - 1) + ((lb + 78) >> 4);
        int wid = threadIdx.x >> 5;
        int t   = threadIdx.x & 31;
        float* bnd = sm + 4 * (RING * 64);     // [5][128]

        int l = (wid < 4) ? wid : (wid - 4);   // local band 0..3
        int w = half * 4 + l;                  // global band
        bool activeBand = (w * 64 < la);
        int lagw = LAG * w;

        if (wid < 4) {
            // ---------------- consumer: 2 rows per lane ----------------
            float* ringW = sm + l * (RING * 64);
            float r0 = BIGV, r1 = BIGV, r0p = BIGV, u0p = BIGV, dprev = 0.0f;
            int row0 = w * 64 + 2 * t;

            for (int sup = 0; sup < nSup; sup++) {
                __syncthreads();
                if (!activeBand) continue;
                int S = (sup - lagw) << 4;
                if (S < 0 || S >= lb + 63) continue;

                float bu[16];
                if (w > 0) {
                    #pragma unroll
                    for (int q = 0; q < 16; q++) bu[q] = bnd[l * 128 + ((S + q) & 127)];
                } else {
                    #pragma unroll
                    for (int q = 0; q < 16; q++) bu[q] = BIGV;
                }

                float2 dv[16];
                int base = S - 2 * t;
                #pragma unroll
                for (int q = 0; q < 16; q++) {
                    int cm = (base + q) & (RING - 1);
                    dv[q] = *(const float2*)&ringW[(cm << 6) + 2 * t];
                }

                if (S >= 63 && S + 16 <= lb) {
                    // -------- interior fast path: all lanes fully active --------
                    #pragma unroll
                    for (int q = 0; q < 16; q++) {
                        float u0 = __shfl_up_sync(0xffffffffu, r1, 1);
                        if (t == 0) u0 = bu[q];
                        float n0 = cellf(dv[q].x, u0p, u0, r0);
                        float n1 = cellf(dprev,  r0p, r0, r1);
                        r0p = r0; r0 = n0;
                        u0p = u0; r1 = n1;
                        dprev = dv[q].y;
                        if (t == 31) bnd[(l + 1) * 128 + ((S + q - 63) & 127)] = r1;
                    }
                } else {
                    // -------- edge path: guarded --------
                    #pragma unroll
                    for (int q = 0; q < 16; q++) {
                        int c0 = base + q;
                        float u0 = __shfl_up_sync(0xffffffffu, r1, 1);
                        if (t == 0) u0 = bu[q];
                        float diag0 = u0p;
                        if (w == 0 && t == 0 && (S + q) == 0) diag0 = 0.0f;
                        float n0 = cellf(dv[q].x, diag0, u0, r0);
                        float n1 = cellf(dprev,  r0p,  r0, r1);
                        bool act0 = ((unsigned)c0 < (unsigned)lb);
                        bool act1 = ((unsigned)(c0 - 1) < (unsigned)lb);
                        r0p = r0;
                        if (act0) r0 = n0;
                        u0p = u0;
                        if (act1) r1 = n1;
                        dprev = dv[q].y;
                        if (act1 && t == 31) bnd[(l + 1) * 128 + ((c0 - 1) & 127)] = r1;
                    }
                }
            }
            if (activeBand) {
                if (row0 == la - 1)     g_sdt[p] = r0;
                if (row0 + 1 == la - 1) g_sdt[p] = r1;
            }
        } else {
            // ---------------- producer: pipelined ring prefetch (+import/export) ----------------
            float* ringP = sm + l * (RING * 64);
            const float* Cp0 = g_costT + (size_t)p * TT * TT + (2 * w) * (TT * 32);
            const float* Cp1 = Cp0 + TT * 32;

            // prologue: global band 0, columns 0..15 (stored directly, before loop)
            if (activeBand && w == 0) {
                const float4* s0 = (const float4*)Cp0;
                const float4* s1 = (const float4*)Cp1;
                #pragma unroll
                for (int k = 0; k < 4; k++) {
                    int i = t + 32 * k;
                    float4 v0 = s0[i];
                    float4 v1 = s1[i];
                    int col = (i >> 3);
                    int r4  = (i & 7) << 2;
                    *(float4*)&ringP[(col << 6) + r4]      = v0;
                    *(float4*)&ringP[(col << 6) + 32 + r4] = v1;
                }
            }

            // preload chunk to be stored at sup=0 (valid only for w==0: cS=16)
            float4 v0r[4], v1r[4];
            int  chunkCS = (0 - lagw) * 16 + 16;
            bool haveChunk = activeBand && (chunkCS >= 0) && (chunkCS < lb);
            if (haveChunk) {
                const float4* s0 = (const float4*)(Cp0 + chunkCS * 32);
                const float4* s1 = (const float4*)(Cp1 + chunkCS * 32);
                #pragma unroll
                for (int k = 0; k < 4; k++) { int i = t + 32 * k; v0r[k] = s0[i]; v1r[k] = s1[i]; }
            }

            for (int sup = 0; sup < nSup; sup++) {
                __syncthreads();

                // importer: block (p,1), band 4: fill bnd[0] for consumer's NEXT superstep
                if (half == 1 && l == 0 && la > 256) {
                    int Snext = ((sup + 1) - lagw) << 4;     // lagw = 20
                    if (Snext >= 0 && Snext < lb) {
                        while (*(volatile int*)&g_prog[p] < sup) __nanosleep(64);
                        __threadfence();
                        int c = Snext + t;
                        if (t < 16 && c < lb) bnd[(c & 127)] = g_bndX[p * TT + c];
                    }
                }

                // store the chunk loaded during the previous superstep (issue-only)
                if (haveChunk) {
                    #pragma unroll
                    for (int k = 0; k < 4; k++) {
                        int i   = t + 32 * k;
                        int cm  = (chunkCS + (i >> 3)) & (RING - 1);
                        int r4  = (i & 7) << 2;
                        *(float4*)&ringP[(cm << 6) + r4]      = v0r[k];
                        *(float4*)&ringP[(cm << 6) + 32 + r4] = v1r[k];
                    }
                }

                // issue LDG for the chunk to store next superstep (latency hidden)
                chunkCS   = ((sup + 1) - lagw) * 16 + 16;
                haveChunk = activeBand && (chunkCS >= 0) && (chunkCS < lb);
                if (haveChunk) {
                    const float4* s0 = (const float4*)(Cp0 + chunkCS * 32);
                    const float4* s1 = (const float4*)(Cp1 + chunkCS * 32);
                    #pragma unroll
                    for (int k = 0; k < 4; k++) { int i = t + 32 * k; v0r[k] = s0[i]; v1r[k] = s1[i]; }
                }

                // exporter: block (p,0), band 3: publish cols written last superstep
                if (half == 0 && l == 3 && la > 256) {
                    int S3 = ((sup - 1) - lagw) << 4;        // lagw = 15
                    int c  = S3 - 63 + t;
                    if (t < 16 && c >= 0 && c < lb) g_bndX[p * TT + c] = bnd[4 * 128 + (c & 127)];
                    __threadfence();
                    if (t == 0) atomicExch(&g_prog[p], sup - 1);
                }
            }
        }
    } else {
        // ---------------- Gram of 44 group vectors (256 threads) ----------------
        int g  = bid - NDTW;                 // 0..120
        int bi = g / 11, bj = g % 11;
        int tid = threadIdx.x;
        const float4* pa[4];
        const float4* pb[4];
        #pragma unroll
        for (int a = 0; a < 4; a++) {
            int ga = bi * 4 + a; int ra = (ga / 11) * 16 + (ga % 11);
            pa[a] = (const float4*)(data + (size_t)ra * TT * DD);
            int gb = bj * 4 + a; int rb = (gb / 11) * 16 + (gb % 11);
            pb[a] = (const float4*)(data + (size_t)rb * TT * DD);
        }
        float acc[4][4];
        #pragma unroll
        for (int a = 0; a < 4; a++)
            #pragma unroll
            for (int b = 0; b < 4; b++) acc[a][b] = 0.0f;

        for (int it = tid; it < TT * DD / 4; it += 256) {
            float4 xa[4], xb[4];
            #pragma unroll
            for (int a = 0; a < 4; a++) xa[a] = pa[a][it];
            #pragma unroll
            for (int b = 0; b < 4; b++) xb[b] = pb[b][it];
            #pragma unroll
            for (int a = 0; a < 4; a++)
                #pragma unroll
                for (int b = 0; b < 4; b++)
                    acc[a][b] += fmaf(xa[a].x, xb[b].x, fmaf(xa[a].y, xb[b].y,
                                 fmaf(xa[a].z, xb[b].z, xa[a].w * xb[b].w)));
        }
        #pragma unroll
        for (int a = 0; a < 4; a++)
            #pragma unroll
            for (int b = 0; b < 4; b++) {
                float v = acc[a][b];
                #pragma unroll
                for (int o = 16; o > 0; o >>= 1) v += __shfl_down_sync(0xffffffffu, v, o);
                acc[a][b] = v;
            }
        int wq = tid >> 5, lane = tid & 31;
        if (lane == 0) {
            #pragma unroll
            for (int a = 0; a < 4; a++)
                #pragma unroll
                for (int b = 0; b < 4; b++) sm[wq * 16 + a * 4 + b] = acc[a][b];
        }
        __syncthreads();
        if (tid < 16) {
            float s = 0.0f;
            #pragma unroll
            for (int ww = 0; ww < 8; ww++) s += sm[ww * 16 + tid];
            int a = tid >> 2, b = tid & 3;
            g_G[(bi * 4 + a) * NGRP + bj * 4 + b] = s;
        }
    }
}

// ======================= MMD (9 warps) + finalize, one block =======================
__global__ __launch_bounds__(512) void mmd_final_kernel(const int* __restrict__ lens,
                                                        float* __restrict__ out) {
    __shared__ float l2s[9][484];
    __shared__ float s_mmd[9];
    int tid  = threadIdx.x;
    int wp   = tid >> 5;
    int lane = tid & 31;

    if (wp < 9) {
        int wa = c_pi[wp], wb = c_pj[wp];
        float part = 0.0f;
        #pragma unroll
        for (int q = 0; q < 16; q++) {
            int e = lane + q * 32;
            if (e < 484) {
                int a = e / 22, b = e % 22;
                int ga = (a < 11) ? wa * 11 + a : wb * 11 + (a - 11);
                int gb = (b < 11) ? wa * 11 + b : wb * 11 + (b - 11);
                float l2 = g_G[ga * NGRP + ga] + g_G[gb * NGRP + gb]
                         - 2.0f * g_G[ga * NGRP + gb];
                l2s[wp][e] = l2;
                part += l2;
            }
        }
        #pragma unroll
        for (int o = 16; o > 0; o >>= 1) part += __shfl_down_sync(0xffffffffu, part, o);
        float bw = __shfl_sync(0xffffffffu, part, 0) / (22.0f * 22.0f - 22.0f) / 4.0f;
        __syncwarp();

        float part2 = 0.0f;
        #pragma unroll
        for (int q = 0; q < 4; q++) {
            int e = lane + q * 32;
            if (e < 121) {
                int u = e / 11, v = e % 11;
                float lxx = l2s[wp][u * 22 + v];
                float lyy = l2s[wp][(u + 11) * 22 + (v + 11)];
                float lxy = l2s[wp][u * 22 + (v + 11)];
                float lyx = l2s[wp][(u + 11) * 22 + v];
                #pragma unroll
                for (int kk = 0; kk < 5; kk++) {
                    float ib = 1.0f / (bw * (float)(1 << kk));
                    part2 += __expf(-lxx * ib) + __expf(-lyy * ib)
                           - __expf(-lxy * ib) - __expf(-lyx * ib);
                }
            }
        }
        #pragma unroll
        for (int o = 16; o > 0; o >>= 1) part2 += __shfl_down_sync(0xffffffffu, part2, o);
        if (lane == 0) s_mmd[wp] = part2 / 121.0f;
    }
    __syncthreads();

    if (tid == 0) {
        float total = 0.0f;
        for (int w = 0; w < 4; w++) {
            float la = (float)lens[w * 16];
            float dg[6], dn[9];
            for (int j = 0; j < 15; j++) {
                float lb = (float)lens[w * 16 + 1 + j];
                float dist = g_sdt[w * 15 + j] / (la + lb);
                if (j < 6) dg[j] = dist; else dn[j - 6] = dist;
            }
            float ca = 0.0f;
            for (int j = 0; j < 6; j++) ca += dg[j];
            ca *= (1.0f / 6.0f);
            float cb = 0.0f;
            for (int j = 0; j < 5; j++) cb += dn[j];
            cb *= (1.0f / 5.0f);
            float lkSum = 0.0f;
            int nz = 0;
            for (int g = 0; g < 6; g++)
                for (int n = 0; n < 9; n++) {
                    float v = dg[g] + 1.0f - dn[n];
                    if (v > 0.0f) { lkSum += v; nz++; }
                }
            float intra = 0.0f;
            for (int g = 0; g < 6; g++) intra += dg[g] - ca;
            float inter = 1.0f - fabsf(ca - cb);
            if (inter < 0.0f) inter = 0.0f;
            total += lkSum / (float)(nz + 1) + intra * 0.1f + inter * 0.1f;
        }
        total *= 0.25f;
        float mx = 0.0f;
        for (int p = 0; p < 9; p++) mx = fmaxf(mx, s_mmd[p]);
        out[0] = total + mx * 0.01f;
    }
}

// ======================= launch =======================
extern "C" void kernel_launch(void* const* d_in, const int* in_sizes, int n_in,
                              void* d_out, int out_size) {
    const float* data = (const float*)d_in[0];
    const int*   lens = (const int*)d_in[1];
    float*       out  = (float*)d_out;

    // rings 4*128*64*4 = 131072 B + bnd 5*128*4 = 2560 B = 133632 B
    // (two blocks would need 267KB > 228KB -> 1 block/SM guaranteed)
    cudaFuncSetAttribute(fused_kernel, cudaFuncAttributeMaxDynamicSharedMemorySize, 133632);

    cost_kernel<<<dim3(8, 4, NPAIR), 256>>>(data, lens);
    fused_kernel<<<NDTW + 121, 256, 133632>>>(data, lens);
    mmd_final_kernel<<<1, 512>>>(lens, out);
}